// round 10
// baseline (speedup 1.0000x reference)
#include <cuda_runtime.h>

#define NB 2048   // batch
#define NS 65     // seq (1 origin + 64 walk)
#define SW 64     // walk length
#define ND 256    // IN_DIM
#define NH 8      // heads
#define NL 256    // head dim L

// Precomputed P @ Wk per head: PKbuf[h][s][l]
__device__ float PKbuf[NH * SW * NL];

__device__ __forceinline__ float sigmoidf(float x) {
    return __fdividef(1.0f, 1.0f + __expf(-x));
}

// Kernel 1: PKbuf[h][s][l] = sum_d P[s][d] * Wk[h][d][l]
__global__ void pk_kernel(const float* __restrict__ P, const float* __restrict__ Wk) {
    const int s = blockIdx.x, h = blockIdx.y, l = threadIdx.x;
    __shared__ float Ps[ND];
    Ps[l] = P[s * ND + l];
    __syncthreads();
    const float* wk = Wk + (size_t)h * ND * NL + l;
    float a0 = 0.f, a1 = 0.f, a2 = 0.f, a3 = 0.f;
#pragma unroll 4
    for (int d = 0; d < ND; d += 4) {
        a0 = fmaf(Ps[d + 0], wk[(d + 0) * NL], a0);
        a1 = fmaf(Ps[d + 1], wk[(d + 1) * NL], a1);
        a2 = fmaf(Ps[d + 2], wk[(d + 2) * NL], a2);
        a3 = fmaf(Ps[d + 3], wk[(d + 3) * NL], a3);
    }
    PKbuf[((size_t)h * SW + s) * NL + l] = (a0 + a1) + (a2 + a3);
}

// Kernel 2: one CTA per batch row. Thread = column l (0..255).
__global__ __launch_bounds__(256, 2)
void wattn_kernel(const float* __restrict__ x,
                  const float* __restrict__ Wq,
                  const float* __restrict__ Wk,
                  const float* __restrict__ Wv,
                  const float* __restrict__ Wvec,   // W[h][l][0] -> [NH*NL]
                  const float* __restrict__ Omat,   // [NH*NL][ND]
                  const float* __restrict__ bias,   // [NH]
                  float* __restrict__ out)          // [NB][2*ND]
{
    extern __shared__ float sm[];
    float* walk     = sm;                    // [SW][ND]  64 KB
    float* origin   = walk + SW * ND;        // [ND]
    float* resall   = origin + ND;           // [NH*NL]   8 KB
    float* scorebuf = resall + NH * NL;      // [SW]
    float* partial  = scorebuf + SW;         // [SW][8]

    const int b = blockIdx.x;
    const int l = threadIdx.x;
    const int warp = l >> 5, lane = l & 31;

    // Load x row: origin + walk (coalesced; walk[s][d] layout matches gmem)
    const float* xb = x + (size_t)b * NS * ND;
    origin[l] = xb[l];
#pragma unroll
    for (int e = 0; e < SW * ND; e += 256) walk[e + l] = xb[ND + e + l];
    __syncthreads();

    for (int h = 0; h < NH; h++) {
        // --- k-logit base: OK[l] = sum_d origin[d] * Wk[h][d][l] ---
        const float* wk = Wk + (size_t)h * ND * NL + l;
        float k0 = 0.f, k1 = 0.f, k2 = 0.f, k3 = 0.f;
#pragma unroll 4
        for (int d = 0; d < ND; d += 4) {
            k0 = fmaf(origin[d + 0], wk[(d + 0) * NL], k0);
            k1 = fmaf(origin[d + 1], wk[(d + 1) * NL], k1);
            k2 = fmaf(origin[d + 2], wk[(d + 2) * NL], k2);
            k3 = fmaf(origin[d + 3], wk[(d + 3) * NL], k3);
        }
        const float okl = (k0 + k1) + (k2 + k3);
        const float wl = Wvec[h * NL + l];
        const float bh = bias[h];

        // --- q-pass: 2 chunks of 32 s-rows; edge -> score partials ---
#pragma unroll
        for (int c = 0; c < 2; c++) {
            float acc[32];
#pragma unroll
            for (int i = 0; i < 32; i++) acc[i] = 0.f;
            const float* wq = Wq + (size_t)h * ND * NL + l;
            const float* wrow = walk + c * 32 * ND;
#pragma unroll 4
            for (int d = 0; d < ND; d++) {
                const float w = wq[d * NL];            // coalesced LDG, L2-resident
#pragma unroll
                for (int i = 0; i < 32; i++)           // broadcast LDS, conflict-free
                    acc[i] = fmaf(wrow[i * ND + d], w, acc[i]);
            }
#pragma unroll
            for (int i = 0; i < 32; i++) {
                const int s = c * 32 + i;
                const float q  = sigmoidf(acc[i]);
                const float kk = sigmoidf(okl + PKbuf[((size_t)h * SW + s) * NL + l]);
                float contrib = (__cosf(kk * q) + bh) * wl;
#pragma unroll
                for (int o = 16; o > 0; o >>= 1)
                    contrib += __shfl_xor_sync(0xffffffffu, contrib, o);
                if (lane == 0) partial[s * 8 + warp] = contrib;
            }
        }
        __syncthreads();

        // --- softmax over s (warp 0, 2 scores per lane) ---
        if (warp == 0) {
            float sc0 = 0.f, sc1 = 0.f;
#pragma unroll
            for (int w = 0; w < 8; w++) {
                sc0 += partial[lane * 8 + w];
                sc1 += partial[(lane + 32) * 8 + w];
            }
            float m = fmaxf(sc0, sc1);
#pragma unroll
            for (int o = 16; o > 0; o >>= 1)
                m = fmaxf(m, __shfl_xor_sync(0xffffffffu, m, o));
            const float e0 = __expf(sc0 - m);
            const float e1 = __expf(sc1 - m);
            float ssum = e0 + e1;
#pragma unroll
            for (int o = 16; o > 0; o >>= 1)
                ssum += __shfl_xor_sync(0xffffffffu, ssum, o);
            const float inv = __fdividef(1.f, ssum);
            scorebuf[lane]      = e0 * inv;
            scorebuf[lane + 32] = e1 * inv;
        }
        __syncthreads();

        // --- v-pass: fold sigmoid(v) directly into res (no v storage) ---
        float r = 0.f;
#pragma unroll
        for (int c = 0; c < 2; c++) {
            float acc[32];
#pragma unroll
            for (int i = 0; i < 32; i++) acc[i] = 0.f;
            const float* wv = Wv + (size_t)h * ND * NL + l;
            const float* wrow = walk + c * 32 * ND;
#pragma unroll 4
            for (int d = 0; d < ND; d++) {
                const float w = wv[d * NL];
#pragma unroll
                for (int i = 0; i < 32; i++)
                    acc[i] = fmaf(wrow[i * ND + d], w, acc[i]);
            }
#pragma unroll
            for (int i = 0; i < 32; i++)
                r = fmaf(sigmoidf(acc[i]), scorebuf[c * 32 + i], r);
        }
        resall[h * NL + l] = r;
        __syncthreads();
    }

    // --- final projection: out[l] = sigmoid(sum_i resall[i] * O[i][l]) ---
    const float* Ob = Omat + l;
    float a0 = 0.f, a1 = 0.f, a2 = 0.f, a3 = 0.f;
#pragma unroll 8
    for (int i = 0; i < NH * NL; i += 4) {
        a0 = fmaf(resall[i + 0], Ob[(size_t)(i + 0) * ND], a0);
        a1 = fmaf(resall[i + 1], Ob[(size_t)(i + 1) * ND], a1);
        a2 = fmaf(resall[i + 2], Ob[(size_t)(i + 2) * ND], a2);
        a3 = fmaf(resall[i + 3], Ob[(size_t)(i + 3) * ND], a3);
    }
    const float o = sigmoidf((a0 + a1) + (a2 + a3));
    float* ob = out + (size_t)b * (2 * ND);
    ob[l]      = o;
    ob[ND + l] = origin[l];
}

static const int SMEM_BYTES = (SW * ND + ND + NH * NL + SW + SW * 8) * (int)sizeof(float);

extern "C" void kernel_launch(void* const* d_in, const int* in_sizes, int n_in,
                              void* d_out, int out_size) {
    const float* x    = (const float*)d_in[0];
    const float* Wq   = (const float*)d_in[1];
    const float* Wk   = (const float*)d_in[2];
    const float* Wv   = (const float*)d_in[3];
    const float* W    = (const float*)d_in[4];
    const float* Omat = (const float*)d_in[5];
    const float* P    = (const float*)d_in[6];
    const float* bias = (const float*)d_in[7];
    float* out = (float*)d_out;

    (void)in_sizes; (void)n_in; (void)out_size;

    dim3 g1(SW, NH);
    pk_kernel<<<g1, 256>>>(P, Wk);

    cudaFuncSetAttribute(wattn_kernel, cudaFuncAttributeMaxDynamicSharedMemorySize, SMEM_BYTES);
    wattn_kernel<<<NB, 256, SMEM_BYTES>>>(x, Wq, Wk, Wv, W, Omat, bias, out);
}

// round 12
// speedup vs baseline: 2.8264x; 2.8264x over previous
#include <cuda_runtime.h>
#include <cuda_bf16.h>
#include <cstdint>

#define NB   2048
#define NSEQ 65
#define SW   64
#define ND   256
#define NH   8
#define NL   256

// ---------------- device scratch ----------------
__device__ float PKT[NH * NL * SW];                          // [h][l][s]
__device__ float okbuf[(size_t)NB * NH * NL];                // [b][h][l]
__device__ __align__(16) __nv_bfloat16 WqT_hi[NH * NL * ND]; // [h][l][d]
__device__ __align__(16) __nv_bfloat16 WqT_lo[NH * NL * ND];
__device__ __align__(16) __nv_bfloat16 WvT_hi[NH * NL * ND];
__device__ __align__(16) __nv_bfloat16 WvT_lo[NH * NL * ND];

// ---------------- smem layout (bytes) ----------------
#define ASTRIDE   264                   // bf16 elems per A row (32*8 + 8 pad -> conflict-free)
#define ABYTES    (128 * ASTRIDE * 2)   // 67584 per part
#define AHI_OFF   0
#define ALO_OFF   67584
#define BB_OFF    135168                // 2 bufs x 2 parts x 20480 = 81920
#define BPART     20480                 // 256 rows x 40 bf16 x 2B
#define SWV_OFF   217088
#define SPART_OFF 218112
#define SSC_OFF   219136
#define SRES_OFF  219648
#define SMEM_TOTAL 221696

__device__ __forceinline__ float sigacc(float x) {
    return __fdividef(1.0f, 1.0f + __expf(-x));
}
// cos on [0,1], deg-8 Taylor, max err ~2.8e-7
__device__ __forceinline__ float cos01(float x) {
    float t = x * x;
    float p = fmaf(t, 2.4801587e-5f, -1.3888889e-3f);
    p = fmaf(t, p, 4.1666668e-2f);
    p = fmaf(t, p, -0.5f);
    return fmaf(t, p, 1.0f);
}
__device__ __forceinline__ uint32_t smem_u32(const void* p) {
    uint32_t a;
    asm("{ .reg .u64 t; cvta.to.shared.u64 t, %1; cvt.u32.u64 %0, t; }" : "=r"(a) : "l"(p));
    return a;
}
__device__ __forceinline__ void ldsm4(uint32_t* r, uint32_t addr) {
    asm volatile("ldmatrix.sync.aligned.m8n8.x4.shared.b16 {%0,%1,%2,%3}, [%4];"
                 : "=r"(r[0]), "=r"(r[1]), "=r"(r[2]), "=r"(r[3]) : "r"(addr));
}
__device__ __forceinline__ void mma_bf16(float* c, const uint32_t* a, const uint32_t* b) {
    asm volatile(
        "mma.sync.aligned.m16n8k16.row.col.f32.bf16.bf16.f32 "
        "{%0,%1,%2,%3}, {%4,%5,%6,%7}, {%8,%9}, {%0,%1,%2,%3};"
        : "+f"(c[0]), "+f"(c[1]), "+f"(c[2]), "+f"(c[3])
        : "r"(a[0]), "r"(a[1]), "r"(a[2]), "r"(a[3]), "r"(b[0]), "r"(b[1]));
}

// ---------------- prep kernels ----------------
__global__ void pk_kernel(const float* __restrict__ P, const float* __restrict__ Wk) {
    const int s = blockIdx.x, h = blockIdx.y, l = threadIdx.x;
    __shared__ float Ps[ND];
    Ps[l] = P[s * ND + l];
    __syncthreads();
    const float* wk = Wk + (size_t)h * ND * NL + l;
    float a0 = 0.f, a1 = 0.f;
#pragma unroll 8
    for (int d = 0; d < ND; d += 2) {
        a0 = fmaf(Ps[d + 0], wk[(d + 0) * NL], a0);
        a1 = fmaf(Ps[d + 1], wk[(d + 1) * NL], a1);
    }
    PKT[((size_t)h * NL + l) * SW + s] = a0 + a1;
}

__global__ void wt_kernel(const float* __restrict__ Wq, const float* __restrict__ Wv) {
    const int dg = blockIdx.x, h = blockIdx.y, m = blockIdx.z;
    const float* W = m ? Wv : Wq;
    __nv_bfloat16* Th = m ? WvT_hi : WqT_hi;
    __nv_bfloat16* Tl = m ? WvT_lo : WqT_lo;
    __shared__ float tile[16][257];
    const int l = threadIdx.x;
#pragma unroll
    for (int r = 0; r < 16; r++)
        tile[r][l] = W[((size_t)h * ND + (dg * 16 + r)) * NL + l];
    __syncthreads();
#pragma unroll
    for (int r = 0; r < 16; r++) {
        float v = tile[r][l];
        __nv_bfloat16 hi = __float2bfloat16(v);
        __nv_bfloat16 lo = __float2bfloat16(v - __bfloat162float(hi));
        size_t o = ((size_t)h * NL + l) * ND + dg * 16 + r;
        Th[o] = hi; Tl[o] = lo;
    }
}

// okbuf[b][h][l] = sum_d origin[b][d] * Wk[h][d][l]; 16 batches per block
__global__ void okb_kernel(const float* __restrict__ x, const float* __restrict__ Wk) {
    const int bg = blockIdx.x, h = blockIdx.y, l = threadIdx.x;
    __shared__ float org[16][ND];
#pragma unroll
    for (int r = 0; r < 16; r++)
        org[r][l] = x[(size_t)(bg * 16 + r) * NSEQ * ND + l];
    __syncthreads();
    const float* wk = Wk + (size_t)h * ND * NL + l;
    float a[16];
#pragma unroll
    for (int r = 0; r < 16; r++) a[r] = 0.f;
    for (int d = 0; d < ND; d++) {
        float w = wk[d * NL];
#pragma unroll
        for (int r = 0; r < 16; r++) a[r] = fmaf(org[r][d], w, a[r]);
    }
#pragma unroll
    for (int r = 0; r < 16; r++)
        okbuf[((size_t)(bg * 16 + r) * NH + h) * NL + l] = a[r];
}

// ---------------- B chunk loader ----------------
__device__ __forceinline__ void loadB(char* sm, int buf,
                                      const __nv_bfloat16* Th, const __nv_bfloat16* Tl,
                                      int c, int tid) {
    char* dh = sm + BB_OFF + buf * (2 * BPART);
    char* dl = dh + BPART;
#pragma unroll
    for (int j = 0; j < 4; j++) {
        int e = j * 256 + tid;
        int row = e >> 2, seg = e & 3;
        const uint4* ph = (const uint4*)(Th + (size_t)row * ND + c * 32);
        const uint4* pl = (const uint4*)(Tl + (size_t)row * ND + c * 32);
        uint32_t d = (uint32_t)(row * 80 + seg * 16);
        *(uint4*)(dh + d) = ph[seg];
        *(uint4*)(dl + d) = pl[seg];
    }
}

// half of one k32 chunk (one k16 step): 8 A-ldsm equiv + 24 B-ldsm + 96 mma
__device__ __forceinline__ void half_chunk(float* acc, uint32_t aRow, uint32_t bRow,
                                           int buf, int c, int k16) {
    uint32_t ah[2][4], al[2][4];
    const uint32_t aoff = (uint32_t)(c * 64 + k16 * 32);
#pragma unroll
    for (int mt = 0; mt < 2; mt++) {
        ldsm4(ah[mt], aRow + aoff + mt * (16 * 528));
        ldsm4(al[mt], aRow + ABYTES + aoff + mt * (16 * 528));
    }
    const uint32_t bo = bRow + buf * (2 * BPART) + k16 * 32;
#pragma unroll
    for (int nt2 = 0; nt2 < 8; nt2++) {
        uint32_t bh4[4], bl4[4];
        ldsm4(bh4, bo + nt2 * (16 * 80));
#pragma unroll
        for (int mt = 0; mt < 2; mt++) {
            mma_bf16(&acc[(mt * 16 + nt2 * 2) * 4],     ah[mt], &bh4[0]);
            mma_bf16(&acc[(mt * 16 + nt2 * 2 + 1) * 4], ah[mt], &bh4[2]);
            mma_bf16(&acc[(mt * 16 + nt2 * 2) * 4],     al[mt], &bh4[0]);
            mma_bf16(&acc[(mt * 16 + nt2 * 2 + 1) * 4], al[mt], &bh4[2]);
        }
        ldsm4(bl4, bo + BPART + nt2 * (16 * 80));
#pragma unroll
        for (int mt = 0; mt < 2; mt++) {
            mma_bf16(&acc[(mt * 16 + nt2 * 2) * 4],     ah[mt], &bl4[0]);
            mma_bf16(&acc[(mt * 16 + nt2 * 2 + 1) * 4], ah[mt], &bl4[2]);
        }
    }
}

// ---------------- main kernel ----------------
__global__ __launch_bounds__(256, 1)
void wattn_mma(const float* __restrict__ x,
               const float* __restrict__ Wvec,
               const float* __restrict__ Omat,
               const float* __restrict__ bias,
               float* __restrict__ out)
{
    extern __shared__ char sm[];
    const uint32_t smb = smem_u32(sm);
    float* sWv   = (float*)(sm + SWV_OFF);
    float* sPart = (float*)(sm + SPART_OFF);
    float* sSc   = (float*)(sm + SSC_OFF);
    float* sRes  = (float*)(sm + SRES_OFF);

    const int tid = threadIdx.x, warp = tid >> 5, lane = tid & 31;
    const int warpM = warp & 3, warpN = warp >> 2;
    const int lr = lane >> 2, lc4 = lane & 3;
    const int b0 = blockIdx.x * 2;
    const int bidx = warpM >> 1;

    // ---- A prep: walk -> bf16 hi/lo, padded rows ----
#pragma unroll 4
    for (int j = 0; j < 64; j++) {
        int p = j * 256 + tid;
        int r = p >> 7;
        int d = (p & 127) * 2;
        int b2 = r >> 6, s = r & 63;
        const float2 v = *(const float2*)(x + ((size_t)(b0 + b2) * NSEQ + 1 + s) * ND + d);
        __nv_bfloat16 h0 = __float2bfloat16(v.x);
        __nv_bfloat16 h1 = __float2bfloat16(v.y);
        __nv_bfloat16 l0 = __float2bfloat16(v.x - __bfloat162float(h0));
        __nv_bfloat16 l1 = __float2bfloat16(v.y - __bfloat162float(h1));
        uint32_t hw = ((uint32_t)__bfloat16_as_ushort(h1) << 16) | __bfloat16_as_ushort(h0);
        uint32_t lw = ((uint32_t)__bfloat16_as_ushort(l1) << 16) | __bfloat16_as_ushort(l0);
        uint32_t off = (uint32_t)(r * 528 + d * 2);
        *(uint32_t*)(sm + AHI_OFF + off) = hw;
        *(uint32_t*)(sm + ALO_OFF + off) = lw;
    }
    __syncthreads();

    // ldmatrix lane base addresses
    const uint32_t aRow = smb + (uint32_t)((warpM * 32 + (lane & 15)) * 528 + (lane >> 4) * 16);
    const uint32_t bRow = smb + BB_OFF +
        (uint32_t)((warpN * 128 + (lane & 7) + ((lane >> 4) << 3)) * 80 + ((lane >> 3) & 1) * 16);

    float outacc0 = 0.f, outacc1 = 0.f;

    for (int h = 0; h < NH; h++) {
        sWv[tid] = Wvec[h * NL + tid];
        const float bh = bias[h];

        for (int mat = 0; mat < 2; mat++) {
            const __nv_bfloat16* Th = (mat ? WvT_hi : WqT_hi) + (size_t)h * NL * ND;
            const __nv_bfloat16* Tl = (mat ? WvT_lo : WqT_lo) + (size_t)h * NL * ND;

            float acc[128];
#pragma unroll
            for (int i = 0; i < 128; i++) acc[i] = 0.f;

            loadB(sm, 0, Th, Tl, 0, tid);
            __syncthreads();
            for (int c = 0; c < 8; c++) {
                const int buf = c & 1;
                half_chunk(acc, aRow, bRow, buf, c, 0);
                if (c < 7) loadB(sm, buf ^ 1, Th, Tl, c + 1, tid);
                half_chunk(acc, aRow, bRow, buf, c, 1);
                __syncthreads();
            }

            if (mat == 0) {
                // ---- q epilogue: scores ----
                const float* okb = okbuf + ((size_t)(b0 + bidx) * NH + h) * NL;
                float part[2][2] = {{0.f, 0.f}, {0.f, 0.f}};
#pragma unroll
                for (int mt = 0; mt < 2; mt++) {
#pragma unroll
                    for (int nt = 0; nt < 16; nt++) {
                        const float* A = &acc[(mt * 16 + nt) * 4];
                        const int col0 = warpN * 128 + nt * 8 + lc4 * 2;
#pragma unroll
                        for (int rh = 0; rh < 2; rh++) {
                            const int srow = (warpM * 32 + mt * 16 + rh * 8 + lr) & 63;
#pragma unroll
                            for (int ci = 0; ci < 2; ci++) {
                                const int col = col0 + ci;
                                float q = sigacc(A[rh * 2 + ci]);
                                float k = sigacc(okb[col] + PKT[((size_t)h * NL + col) * SW + srow]);
                                part[mt][rh] = fmaf(cos01(k * q) + bh, sWv[col], part[mt][rh]);
                            }
                        }
                    }
                }
#pragma unroll
                for (int mt = 0; mt < 2; mt++)
#pragma unroll
                    for (int rh = 0; rh < 2; rh++) {
                        float v = part[mt][rh];
                        v += __shfl_xor_sync(0xffffffffu, v, 1);
                        v += __shfl_xor_sync(0xffffffffu, v, 2);
                        if (lc4 == 0)
                            sPart[(warpM * 32 + mt * 16 + rh * 8 + lr) * 2 + warpN] = v;
                    }
                __syncthreads();
                // softmax (warp 0: batch 0, warp 1: batch 1) + zero sRes
                if (warp < 2) {
                    const int rb = warp * 64;
                    float sc0 = sPart[(rb + lane) * 2] + sPart[(rb + lane) * 2 + 1];
                    float sc1 = sPart[(rb + lane + 32) * 2] + sPart[(rb + lane + 32) * 2 + 1];
                    float m = fmaxf(sc0, sc1);
#pragma unroll
                    for (int o = 16; o > 0; o >>= 1)
                        m = fmaxf(m, __shfl_xor_sync(0xffffffffu, m, o));
                    float e0 = __expf(sc0 - m), e1 = __expf(sc1 - m);
                    float ss = e0 + e1;
#pragma unroll
                    for (int o = 16; o > 0; o >>= 1)
                        ss += __shfl_xor_sync(0xffffffffu, ss, o);
                    float inv = __fdividef(1.f, ss);
                    sSc[rb + lane]      = e0 * inv;
                    sSc[rb + lane + 32] = e1 * inv;
                }
                sRes[tid] = 0.f;
                sRes[256 + tid] = 0.f;
                __syncthreads();
            } else {
                // ---- v epilogue: res[b][l] += score[s] * sigmoid(v[s][l]) ----
#pragma unroll
                for (int mt = 0; mt < 2; mt++) {
                    const int rbase = warpM * 32 + mt * 16 + lr;
                    const float sc0 = sSc[rbase], sc1 = sSc[rbase + 8];
#pragma unroll
                    for (int nt = 0; nt < 16; nt++) {
                        const float* A = &acc[(mt * 16 + nt) * 4];
                        float v0 = fmaf(sigacc(A[0]), sc0, sigacc(A[2]) * sc1);
                        float v1 = fmaf(sigacc(A[1]), sc0, sigacc(A[3]) * sc1);
#pragma unroll
                        for (int o = 4; o <= 16; o <<= 1) {
                            v0 += __shfl_xor_sync(0xffffffffu, v0, o);
                            v1 += __shfl_xor_sync(0xffffffffu, v1, o);
                        }
                        if (lr == 0) {
                            const int col0 = warpN * 128 + nt * 8 + lc4 * 2;
                            atomicAdd(&sRes[bidx * 256 + col0], v0);
                            atomicAdd(&sRes[bidx * 256 + col0 + 1], v1);
                        }
                    }
                }
                __syncthreads();
            }
        }

        // ---- O-projection partial (fp32) ----
        {
            const float* Ob = Omat + (size_t)h * NL * ND + tid;
#pragma unroll 8
            for (int i = 0; i < NL; i++) {
                float w = Ob[(size_t)i * ND];
                outacc0 = fmaf(sRes[i], w, outacc0);
                outacc1 = fmaf(sRes[256 + i], w, outacc1);
            }
        }
        __syncthreads();
    }

    // ---- output ----
    float* o0 = out + (size_t)b0 * (2 * ND);
    float* o1 = o0 + 2 * ND;
    o0[tid] = sigacc(outacc0);
    o1[tid] = sigacc(outacc1);
    o0[ND + tid] = x[(size_t)b0 * NSEQ * ND + tid];
    o1[ND + tid] = x[(size_t)(b0 + 1) * NSEQ * ND + tid];
}

extern "C" void kernel_launch(void* const* d_in, const int* in_sizes, int n_in,
                              void* d_out, int out_size) {
    const float* x    = (const float*)d_in[0];
    const float* Wq   = (const float*)d_in[1];
    const float* Wk   = (const float*)d_in[2];
    const float* Wv   = (const float*)d_in[3];
    const float* W    = (const float*)d_in[4];
    const float* Omat = (const float*)d_in[5];
    const float* P    = (const float*)d_in[6];
    const float* bias = (const float*)d_in[7];
    float* out = (float*)d_out;
    (void)in_sizes; (void)n_in; (void)out_size;

    dim3 gpk(SW, NH);
    pk_kernel<<<gpk, 256>>>(P, Wk);
    dim3 gwt(16, NH, 2);
    wt_kernel<<<gwt, 256>>>(Wq, Wv);
    dim3 gok(NB / 16, NH);
    okb_kernel<<<gok, 256>>>(x, Wk);

    cudaFuncSetAttribute(wattn_mma, cudaFuncAttributeMaxDynamicSharedMemorySize, SMEM_TOTAL);
    wattn_mma<<<NB / 2, 256, SMEM_TOTAL>>>(x, W, Omat, bias, out);
}

// round 16
// speedup vs baseline: 3.1424x; 1.1118x over previous
#include <cuda_runtime.h>
#include <cuda_bf16.h>
#include <cstdint>

#define NB   2048
#define NSEQ 65
#define SW   64
#define ND   256
#define NH   8
#define NL   256

// ---------------- device scratch ----------------
__device__ float PKT[NH * NL * SW];                          // [h][l][s]
__device__ float okbuf[(size_t)NB * NH * NL];                // [b][h][l]
__device__ __align__(16) __nv_bfloat16 WqT_hi[NH * NL * ND]; // [h][l][d]
__device__ __align__(16) __nv_bfloat16 WqT_lo[NH * NL * ND];
__device__ __align__(16) __nv_bfloat16 WvT_hi[NH * NL * ND];
__device__ __align__(16) __nv_bfloat16 WvT_lo[NH * NL * ND];

// ---------------- smem layout (bytes) ----------------
#define ASTRIDE   528                   // bytes per A row (256 bf16 + 8 pad)
#define ABYTES    (128 * ASTRIDE)       // 67584 per part
#define AHI_OFF   0
#define ALO_OFF   67584
#define BB_OFF    135168                // 2 bufs x 2 parts x 20480 = 81920
#define BPART     20480                 // 256 rows x 80 B (32 bf16 + 16B pad)
#define SWV_OFF   217088                // float[256]
#define SPART_OFF 218112                // float[128*4]
#define SSC_OFF   220160                // float[128]
#define SRES_OFF  220672                // float[512]
#define SMEM_TOTAL 222720

__device__ __forceinline__ float sigacc(float x) {
    return __fdividef(1.0f, 1.0f + __expf(-x));
}
// cos on [0,1], deg-8 Taylor, max err ~2.8e-7
__device__ __forceinline__ float cos01(float x) {
    float t = x * x;
    float p = fmaf(t, 2.4801587e-5f, -1.3888889e-3f);
    p = fmaf(t, p, 4.1666668e-2f);
    p = fmaf(t, p, -0.5f);
    return fmaf(t, p, 1.0f);
}
__device__ __forceinline__ uint32_t smem_u32(const void* p) {
    uint32_t a;
    asm("{ .reg .u64 t; cvta.to.shared.u64 t, %1; cvt.u32.u64 %0, t; }" : "=r"(a) : "l"(p));
    return a;
}
__device__ __forceinline__ void ldsm4(uint32_t* r, uint32_t addr) {
    asm volatile("ldmatrix.sync.aligned.m8n8.x4.shared.b16 {%0,%1,%2,%3}, [%4];"
                 : "=r"(r[0]), "=r"(r[1]), "=r"(r[2]), "=r"(r[3]) : "r"(addr));
}
__device__ __forceinline__ void mma_bf16(float* c, const uint32_t* a, const uint32_t* b) {
    asm volatile(
        "mma.sync.aligned.m16n8k16.row.col.f32.bf16.bf16.f32 "
        "{%0,%1,%2,%3}, {%4,%5,%6,%7}, {%8,%9}, {%0,%1,%2,%3};"
        : "+f"(c[0]), "+f"(c[1]), "+f"(c[2]), "+f"(c[3])
        : "r"(a[0]), "r"(a[1]), "r"(a[2]), "r"(a[3]), "r"(b[0]), "r"(b[1]));
}

// ---------------- prep kernels ----------------
__global__ void pk_kernel(const float* __restrict__ P, const float* __restrict__ Wk) {
    const int s = blockIdx.x, h = blockIdx.y, l = threadIdx.x;
    __shared__ float Ps[ND];
    Ps[l] = P[s * ND + l];
    __syncthreads();
    const float* wk = Wk + (size_t)h * ND * NL + l;
    float a0 = 0.f, a1 = 0.f;
#pragma unroll 8
    for (int d = 0; d < ND; d += 2) {
        a0 = fmaf(Ps[d + 0], wk[(d + 0) * NL], a0);
        a1 = fmaf(Ps[d + 1], wk[(d + 1) * NL], a1);
    }
    PKT[((size_t)h * NL + l) * SW + s] = a0 + a1;
}

__global__ void wt_kernel(const float* __restrict__ Wq, const float* __restrict__ Wv) {
    const int dg = blockIdx.x, h = blockIdx.y, m = blockIdx.z;
    const float* W = m ? Wv : Wq;
    __nv_bfloat16* Th = m ? WvT_hi : WqT_hi;
    __nv_bfloat16* Tl = m ? WvT_lo : WqT_lo;
    __shared__ float tile[16][257];
    const int l = threadIdx.x;
#pragma unroll
    for (int r = 0; r < 16; r++)
        tile[r][l] = W[((size_t)h * ND + (dg * 16 + r)) * NL + l];
    __syncthreads();
#pragma unroll
    for (int r = 0; r < 16; r++) {
        float v = tile[r][l];
        __nv_bfloat16 hi = __float2bfloat16(v);
        __nv_bfloat16 lo = __float2bfloat16(v - __bfloat162float(hi));
        size_t o = ((size_t)h * NL + l) * ND + dg * 16 + r;
        Th[o] = hi; Tl[o] = lo;
    }
}

__global__ void okb_kernel(const float* __restrict__ x, const float* __restrict__ Wk) {
    const int bg = blockIdx.x, h = blockIdx.y, l = threadIdx.x;
    __shared__ float org[16][ND];
#pragma unroll
    for (int r = 0; r < 16; r++)
        org[r][l] = x[(size_t)(bg * 16 + r) * NSEQ * ND + l];
    __syncthreads();
    const float* wk = Wk + (size_t)h * ND * NL + l;
    float a[16];
#pragma unroll
    for (int r = 0; r < 16; r++) a[r] = 0.f;
    for (int d = 0; d < ND; d++) {
        float w = wk[d * NL];
#pragma unroll
        for (int r = 0; r < 16; r++) a[r] = fmaf(org[r][d], w, a[r]);
    }
#pragma unroll
    for (int r = 0; r < 16; r++)
        okbuf[((size_t)(bg * 16 + r) * NH + h) * NL + l] = a[r];
}

// ---------------- B chunk prefetch via cp.async ----------------
__device__ __forceinline__ void prefetchB(uint32_t smb, int buf, int it, int c, int tid) {
    const int h = it >> 1, mat = it & 1;
    const __nv_bfloat16* Th = (mat ? WvT_hi : WqT_hi) + (size_t)h * NL * ND;
    const __nv_bfloat16* Tl = (mat ? WvT_lo : WqT_lo) + (size_t)h * NL * ND;
    const uint32_t dbase = smb + BB_OFF + (uint32_t)buf * (2 * BPART);
#pragma unroll
    for (int j = 0; j < 4; j++) {
        const int part = j >> 1;
        const int rem = ((j & 1) << 9) | tid;
        const int row = rem >> 2, seg = rem & 3;
        const __nv_bfloat16* src = (part ? Tl : Th) + (size_t)row * ND + c * 32 + seg * 8;
        const uint32_t dst = dbase + (uint32_t)(part * BPART + row * 80 + seg * 16);
        asm volatile("cp.async.ca.shared.global [%0], [%1], 16;" :: "r"(dst), "l"(src));
    }
    asm volatile("cp.async.commit_group;" ::: "memory");
}

// one k16 step: 4 A-ldsm + 8 B-ldsm + 48 mma
__device__ __forceinline__ void half_chunk(float* acc, uint32_t aRow, uint32_t bRow,
                                           uint32_t bufoff, int c, int k16) {
    uint32_t ah[2][4], al[2][4];
    const uint32_t aoff = (uint32_t)(c * 64 + k16 * 32);
#pragma unroll
    for (int mt = 0; mt < 2; mt++) {
        ldsm4(ah[mt], aRow + aoff + mt * (16 * ASTRIDE));
        ldsm4(al[mt], aRow + ABYTES + aoff + mt * (16 * ASTRIDE));
    }
    const uint32_t bo = bRow + bufoff + k16 * 32;
#pragma unroll
    for (int nt2 = 0; nt2 < 4; nt2++) {
        uint32_t bh4[4], bl4[4];
        ldsm4(bh4, bo + nt2 * (16 * 80));
#pragma unroll
        for (int mt = 0; mt < 2; mt++) {
            mma_bf16(&acc[(mt * 8 + nt2 * 2) * 4],     ah[mt], &bh4[0]);
            mma_bf16(&acc[(mt * 8 + nt2 * 2 + 1) * 4], ah[mt], &bh4[2]);
            mma_bf16(&acc[(mt * 8 + nt2 * 2) * 4],     al[mt], &bh4[0]);
            mma_bf16(&acc[(mt * 8 + nt2 * 2 + 1) * 4], al[mt], &bh4[2]);
        }
        ldsm4(bl4, bo + BPART + nt2 * (16 * 80));
#pragma unroll
        for (int mt = 0; mt < 2; mt++) {
            mma_bf16(&acc[(mt * 8 + nt2 * 2) * 4],     ah[mt], &bl4[0]);
            mma_bf16(&acc[(mt * 8 + nt2 * 2 + 1) * 4], ah[mt], &bl4[2]);
        }
    }
}

// ---------------- main kernel: 512 threads, 16 warps (4x4) ----------------
__global__ __launch_bounds__(512, 1)
void wattn_mma(const float* __restrict__ x,
               const float* __restrict__ Wvec,
               const float* __restrict__ Omat,
               const float* __restrict__ bias,
               float* __restrict__ out)
{
    extern __shared__ char sm[];
    const uint32_t smb = smem_u32(sm);
    float* sWv   = (float*)(sm + SWV_OFF);
    float* sPart = (float*)(sm + SPART_OFF);
    float* sSc   = (float*)(sm + SSC_OFF);
    float* sRes  = (float*)(sm + SRES_OFF);

    const int tid = threadIdx.x, warp = tid >> 5, lane = tid & 31;
    const int warpM = warp & 3, warpN = warp >> 2;
    const int lr = lane >> 2, lc4 = lane & 3;
    const int b0 = blockIdx.x * 2;
    const int bidx = warpM >> 1;

    // prefetch first B chunk immediately (overlaps A prep)
    prefetchB(smb, 0, 0, 0, tid);

    // ---- A prep: walk -> bf16 hi/lo, padded rows ----
#pragma unroll 4
    for (int j = 0; j < 32; j++) {
        int p = j * 512 + tid;
        int r = p >> 7;
        int d = (p & 127) * 2;
        int b2 = r >> 6, s = r & 63;
        const float2 v = *(const float2*)(x + ((size_t)(b0 + b2) * NSEQ + 1 + s) * ND + d);
        __nv_bfloat16 h0 = __float2bfloat16(v.x);
        __nv_bfloat16 h1 = __float2bfloat16(v.y);
        __nv_bfloat16 l0 = __float2bfloat16(v.x - __bfloat162float(h0));
        __nv_bfloat16 l1 = __float2bfloat16(v.y - __bfloat162float(h1));
        uint32_t hw = ((uint32_t)__bfloat16_as_ushort(h1) << 16) | __bfloat16_as_ushort(h0);
        uint32_t lw = ((uint32_t)__bfloat16_as_ushort(l1) << 16) | __bfloat16_as_ushort(l0);
        uint32_t off = (uint32_t)(r * ASTRIDE + d * 2);
        *(uint32_t*)(sm + AHI_OFF + off) = hw;
        *(uint32_t*)(sm + ALO_OFF + off) = lw;
    }
    __syncthreads();

    // ldmatrix lane base addresses
    const uint32_t aRow = smb + (uint32_t)((warpM * 32 + (lane & 15)) * ASTRIDE + (lane >> 4) * 16);
    const uint32_t bRow = smb + BB_OFF +
        (uint32_t)((warpN * 64 + (lane & 7) + ((lane >> 4) << 3)) * 80 + ((lane >> 3) & 1) * 16);

    float outacc = 0.f;
    int gc = 0;

    for (int it = 0; it < 16; it++) {
        const int h = it >> 1, mat = it & 1;
        if (mat == 0 && tid < 256) sWv[tid] = Wvec[h * NL + tid];

        float acc[64];
#pragma unroll
        for (int i = 0; i < 64; i++) acc[i] = 0.f;

        for (int c = 0; c < 8; c++) {
            const int buf = gc & 1;
            asm volatile("cp.async.wait_group 0;" ::: "memory");
            __syncthreads();
            if (c < 7)       prefetchB(smb, buf ^ 1, it, c + 1, tid);
            else if (it < 15) prefetchB(smb, buf ^ 1, it + 1, 0, tid);
            const uint32_t bufoff = (uint32_t)buf * (2 * BPART);
            half_chunk(acc, aRow, bRow, bufoff, c, 0);
            half_chunk(acc, aRow, bRow, bufoff, c, 1);
            gc++;
        }

        if (mat == 0) {
            // ---- q epilogue: scores ----
            const float bh = bias[h];
            const float* okb = okbuf + ((size_t)(b0 + bidx) * NH + h) * NL;
            float part[2][2] = {{0.f, 0.f}, {0.f, 0.f}};
#pragma unroll
            for (int mt = 0; mt < 2; mt++) {
#pragma unroll
                for (int nt = 0; nt < 8; nt++) {
                    const float* A = &acc[(mt * 8 + nt) * 4];
                    const int col0 = warpN * 64 + nt * 8 + lc4 * 2;
#pragma unroll
                    for (int rh = 0; rh < 2; rh++) {
                        const int srow = (warpM * 32 + mt * 16 + rh * 8 + lr) & 63;
#pragma unroll
                        for (int ci = 0; ci < 2; ci++) {
                            const int col = col0 + ci;
                            float q = sigacc(A[rh * 2 + ci]);
                            float k = sigacc(okb[col] + PKT[((size_t)h * NL + col) * SW + srow]);
                            part[mt][rh] = fmaf(cos01(k * q) + bh, sWv[col], part[mt][rh]);
                        }
                    }
                }
            }
#pragma unroll
            for (int mt = 0; mt < 2; mt++)
#pragma unroll
                for (int rh = 0; rh < 2; rh++) {
                    float v = part[mt][rh];
                    v += __shfl_xor_sync(0xffffffffu, v, 1);
                    v += __shfl_xor_sync(0xffffffffu, v, 2);
                    if (lc4 == 0)
                        sPart[(warpM * 32 + mt * 16 + rh * 8 + lr) * 4 + warpN] = v;
                }
            __syncthreads();
            if (warp < 2) {
                const int rb = warp * 64;
                float sc0 = 0.f, sc1 = 0.f;
#pragma unroll
                for (int w = 0; w < 4; w++) {
                    sc0 += sPart[(rb + lane) * 4 + w];
                    sc1 += sPart[(rb + lane + 32) * 4 + w];
                }
                float m = fmaxf(sc0, sc1);
#pragma unroll
                for (int o = 16; o > 0; o >>= 1)
                    m = fmaxf(m, __shfl_xor_sync(0xffffffffu, m, o));
                float e0 = __expf(sc0 - m), e1 = __expf(sc1 - m);
                float ss = e0 + e1;
#pragma unroll
                for (int o = 16; o > 0; o >>= 1)
                    ss += __shfl_xor_sync(0xffffffffu, ss, o);
                float inv = __fdividef(1.f, ss);
                sSc[rb + lane]      = e0 * inv;
                sSc[rb + lane + 32] = e1 * inv;
            }
            sRes[tid] = 0.f;
            __syncthreads();
        } else {
            // ---- v epilogue ----
#pragma unroll
            for (int mt = 0; mt < 2; mt++) {
                const int rbase = warpM * 32 + mt * 16 + lr;
                const float sc0 = sSc[rbase], sc1 = sSc[rbase + 8];
#pragma unroll
                for (int nt = 0; nt < 8; nt++) {
                    const float* A = &acc[(mt * 8 + nt) * 4];
                    float v0 = fmaf(sigacc(A[0]), sc0, sigacc(A[2]) * sc1);
                    float v1 = fmaf(sigacc(A[1]), sc0, sigacc(A[3]) * sc1);
#pragma unroll
                    for (int o = 4; o <= 16; o <<= 1) {
                        v0 += __shfl_xor_sync(0xffffffffu, v0, o);
                        v1 += __shfl_xor_sync(0xffffffffu, v1, o);
                    }
                    if (lr == 0) {
                        const int col0 = warpN * 64 + nt * 8 + lc4 * 2;
                        atomicAdd(&sRes[bidx * 256 + col0], v0);
                        atomicAdd(&sRes[bidx * 256 + col0 + 1], v1);
                    }
                }
            }
            __syncthreads();
            // ---- O-projection partial (fp32) ----
            {
                const int bsel = tid >> 8, col = tid & 255;
                const float* Ob = Omat + (size_t)h * NL * ND + col;
                const float* rs = sRes + bsel * 256;
                float a0 = 0.f, a1 = 0.f;
#pragma unroll 8
                for (int i = 0; i < NL; i += 2) {
                    a0 = fmaf(rs[i],     Ob[(size_t)i * ND],       a0);
                    a1 = fmaf(rs[i + 1], Ob[(size_t)(i + 1) * ND], a1);
                }
                outacc += a0 + a1;
            }
            __syncthreads();
        }
    }

    // ---- output ----
    const int bsel = tid >> 8, col = tid & 255;
    float* o = out + (size_t)(b0 + bsel) * (2 * ND);
    o[col]      = sigacc(outacc);
    o[ND + col] = x[(size_t)(b0 + bsel) * NSEQ * ND + col];
}

extern "C" void kernel_launch(void* const* d_in, const int* in_sizes, int n_in,
                              void* d_out, int out_size) {
    const float* x    = (const float*)d_in[0];
    const float* Wq   = (const float*)d_in[1];
    const float* Wk   = (const float*)d_in[2];
    const float* Wv   = (const float*)d_in[3];
    const float* W    = (const float*)d_in[4];
    const float* Omat = (const float*)d_in[5];
    const float* P    = (const float*)d_in[6];
    const float* bias = (const float*)d_in[7];
    float* out = (float*)d_out;
    (void)in_sizes; (void)n_in; (void)out_size;

    dim3 gpk(SW, NH);
    pk_kernel<<<gpk, 256>>>(P, Wk);
    dim3 gwt(16, NH, 2);
    wt_kernel<<<gwt, 256>>>(Wq, Wv);
    dim3 gok(NB / 16, NH);
    okb_kernel<<<gok, 256>>>(x, Wk);

    cudaFuncSetAttribute(wattn_mma, cudaFuncAttributeMaxDynamicSharedMemorySize, SMEM_TOTAL);
    wattn_mma<<<NB / 2, 512, SMEM_TOTAL>>>(x, W, Omat, bias, out);
}